// round 3
// baseline (speedup 1.0000x reference)
#include <cuda_runtime.h>

#define B_ 64
#define S_ 512
#define H_ 1024
#define L_ 5

// Scratch (static device arrays; no allocation).
__device__ float    g_em[S_ * B_ * 8];          // emissions, time-major, padded to 8 floats
__device__ unsigned g_bp[(S_ - 1) * B_];        // packed Viterbi backpointers (3 bits x 5 states)

#define SEL5(a0, a1, a2, a3, a4, i) \
    ((i) == 0 ? (a0) : (i) == 1 ? (a1) : (i) == 2 ? (a2) : (i) == 3 ? (a3) : (a4))

// ---------------------------------------------------------------------------
// Kernel 1: emissions = relu(feats @ W + b), written as g_em[t][b][l(8)]
// One warp computes 4 full rows; W transposed in shared so each float4 of W
// feeds 4 rows (16 MACs) -> smem traffic 1.25x of feats traffic. HBM-bound.
// ---------------------------------------------------------------------------
__global__ __launch_bounds__(256) void k_emit(const float* __restrict__ feats,
                                              const float* __restrict__ W,
                                              const float* __restrict__ bias) {
    __shared__ float sw[L_ * H_];   // sw[l*H + h] = W[h*L + l]
    int tid = threadIdx.x;
    for (int i = tid; i < L_ * H_; i += 256) {
        int h = i / L_, l = i % L_;
        sw[l * H_ + h] = W[i];
    }
    __syncthreads();

    int warp = tid >> 5, lane = tid & 31;
    int r0 = (blockIdx.x * 8 + warp) * 4;      // 4 consecutive rows per warp

    float acc[4][5];
#pragma unroll
    for (int r = 0; r < 4; r++)
#pragma unroll
        for (int l = 0; l < 5; l++) acc[r][l] = 0.f;

#pragma unroll 1
    for (int k = 0; k < 8; k++) {
        int col = k * 128 + lane * 4;
        float4 x[4];
#pragma unroll
        for (int r = 0; r < 4; r++)
            x[r] = *reinterpret_cast<const float4*>(feats + (size_t)(r0 + r) * H_ + col);
#pragma unroll
        for (int l = 0; l < 5; l++) {
            float4 w = *reinterpret_cast<const float4*>(sw + l * H_ + col);
#pragma unroll
            for (int r = 0; r < 4; r++)
                acc[r][l] = fmaf(x[r].w, w.w,
                            fmaf(x[r].z, w.z,
                            fmaf(x[r].y, w.y,
                            fmaf(x[r].x, w.x, acc[r][l]))));
        }
    }

    // butterfly reduce each of the 20 partial sums across the warp
#pragma unroll
    for (int r = 0; r < 4; r++)
#pragma unroll
        for (int l = 0; l < 5; l++) {
#pragma unroll
            for (int off = 16; off > 0; off >>= 1)
                acc[r][l] += __shfl_xor_sync(0xffffffffu, acc[r][l], off);
        }

    if (lane == 0) {
        float bb[5];
#pragma unroll
        for (int l = 0; l < 5; l++) bb[l] = __ldg(bias + l);
#pragma unroll
        for (int r = 0; r < 4; r++) {
            int row = r0 + r;
            int b = row >> 9;        // row / 512
            int s = row & 511;       // row % 512
#pragma unroll
            for (int l = 0; l < 5; l++) {
                float v = acc[r][l] + bb[l];
                g_em[(s * B_ + b) * 8 + l] = v > 0.f ? v : 0.f;
            }
        }
    }
}

// ---------------------------------------------------------------------------
// Kernel 2: grid of 2 blocks, 64 threads each (thread = batch).
//   block 0: CRF forward (log-partition) + gold-path numerator + loss
//   block 1: Viterbi + backtrace + paths
// Both run concurrently on different SMs.
// ---------------------------------------------------------------------------
__global__ __launch_bounds__(64) void k_crf(const int* __restrict__ labels,
                                            const float* __restrict__ start_t,
                                            const float* __restrict__ end_t,
                                            const float* __restrict__ trans,
                                            const float* __restrict__ weights,
                                            float* __restrict__ out,
                                            int loss_off, int path_off) {
    __shared__ float s_trans[25];
    __shared__ float s_red[2];
    int b = threadIdx.x;
    if (b < 25) s_trans[b] = __ldg(trans + b);
    __syncthreads();

    if (blockIdx.x == 0) {
        // ---------------- forward + numerator + loss ----------------
        float E[25];
#pragma unroll
        for (int i = 0; i < 25; i++) E[i] = __expf(s_trans[i]);
        float st[5], en[5], wt[5];
#pragma unroll
        for (int l = 0; l < 5; l++) {
            st[l] = __ldg(start_t + l);
            en[l] = __ldg(end_t + l);
            wt[l] = __ldg(weights + l);
        }

        // t = 0
        float4 e0  = *reinterpret_cast<const float4*>(g_em + b * 8);
        float  e0h = g_em[b * 8 + 4];
        int lab = __ldg(labels + b * S_);
        float a[5] = { st[0] + e0.x, st[1] + e0.y, st[2] + e0.z, st[3] + e0.w, st[4] + e0h };
        float emt = SEL5(e0.x, e0.y, e0.z, e0.w, e0h, lab);
        float ws  = SEL5(wt[0], wt[1], wt[2], wt[3], wt[4], lab);
        float num = SEL5(st[0], st[1], st[2], st[3], st[4], lab) + ws * emt;
        int labp = lab;

        // software-pipelined main loop, chunks of 4, double-buffered prefetch
        float4 Alo[4]; float Ahi[4]; int Alab[4];
#pragma unroll
        for (int d = 0; d < 4; d++) {
            int t = 1 + d;
            Alo[d]  = *reinterpret_cast<const float4*>(g_em + (t * B_ + b) * 8);
            Ahi[d]  = g_em[(t * B_ + b) * 8 + 4];
            Alab[d] = __ldg(labels + b * S_ + t);
        }

#pragma unroll 1
        for (int tb = 1; tb < S_; tb += 4) {
            float4 Blo[4]; float Bhi[4]; int Blab[4];
#pragma unroll
            for (int d = 0; d < 4; d++) {
                int t = tb + 4 + d;
                if (t < S_) {
                    Blo[d]  = *reinterpret_cast<const float4*>(g_em + (t * B_ + b) * 8);
                    Bhi[d]  = g_em[(t * B_ + b) * 8 + 4];
                    Blab[d] = __ldg(labels + b * S_ + t);
                }
            }
#pragma unroll
            for (int d = 0; d < 4; d++) {
                int t = tb + d;
                if (t < S_) {
                    float em0 = Alo[d].x, em1 = Alo[d].y, em2 = Alo[d].z,
                          em3 = Alo[d].w, em4 = Ahi[d];
                    int lb = Alab[d];
                    float a0 = a[0];
                    float c1 = __expf(a[1] - a0);
                    float c2 = __expf(a[2] - a0);
                    float c3 = __expf(a[3] - a0);
                    float c4 = __expf(a[4] - a0);
                    float na[5];
#pragma unroll
                    for (int j = 0; j < 5; j++) {
                        float s = fmaf(c4, E[20 + j],
                                  fmaf(c3, E[15 + j],
                                  fmaf(c2, E[10 + j],
                                  fmaf(c1, E[5 + j], E[j]))));
                        na[j] = a0 + __logf(s);
                    }
                    a[0] = na[0] + em0; a[1] = na[1] + em1; a[2] = na[2] + em2;
                    a[3] = na[3] + em3; a[4] = na[4] + em4;

                    // numerator (off the alpha chain)
                    float emv = SEL5(em0, em1, em2, em3, em4, lb);
                    float wv  = SEL5(wt[0], wt[1], wt[2], wt[3], wt[4], lb);
                    num = fmaf(wv, emv, num) + s_trans[labp * 5 + lb];
                    labp = lb;
                }
            }
#pragma unroll
            for (int d = 0; d < 4; d++) { Alo[d] = Blo[d]; Ahi[d] = Bhi[d]; Alab[d] = Blab[d]; }
        }

        num += SEL5(en[0], en[1], en[2], en[3], en[4], labp);

        float base = a[0] + en[0];
        float zs = 1.f + __expf(a[1] + en[1] - base) + __expf(a[2] + en[2] - base)
                       + __expf(a[3] + en[3] - base) + __expf(a[4] + en[4] - base);
        float logZ = base + __logf(zs);

        float dlt = num - logZ;
#pragma unroll
        for (int off = 16; off > 0; off >>= 1)
            dlt += __shfl_xor_sync(0xffffffffu, dlt, off);
        if ((b & 31) == 0) s_red[b >> 5] = dlt;
        __syncthreads();
        if (b == 0 && loss_off >= 0)
            out[loss_off] = -(s_red[0] + s_red[1]) * (1.0f / 32768.0f);

    } else {
        // ---------------- Viterbi + backtrace ----------------
        float T[25];
#pragma unroll
        for (int i = 0; i < 25; i++) T[i] = s_trans[i];
        float st[5], en[5];
#pragma unroll
        for (int l = 0; l < 5; l++) { st[l] = __ldg(start_t + l); en[l] = __ldg(end_t + l); }

        float4 e0  = *reinterpret_cast<const float4*>(g_em + b * 8);
        float  e0h = g_em[b * 8 + 4];
        float v[5] = { st[0] + e0.x, st[1] + e0.y, st[2] + e0.z, st[3] + e0.w, st[4] + e0h };

        float4 Alo[4]; float Ahi[4];
#pragma unroll
        for (int d = 0; d < 4; d++) {
            int t = 1 + d;
            Alo[d] = *reinterpret_cast<const float4*>(g_em + (t * B_ + b) * 8);
            Ahi[d] = g_em[(t * B_ + b) * 8 + 4];
        }

#pragma unroll 1
        for (int tb = 1; tb < S_; tb += 4) {
            float4 Blo[4]; float Bhi[4];
#pragma unroll
            for (int d = 0; d < 4; d++) {
                int t = tb + 4 + d;
                if (t < S_) {
                    Blo[d] = *reinterpret_cast<const float4*>(g_em + (t * B_ + b) * 8);
                    Bhi[d] = g_em[(t * B_ + b) * 8 + 4];
                }
            }
#pragma unroll
            for (int d = 0; d < 4; d++) {
                int t = tb + d;
                if (t < S_) {
                    float em[5] = { Alo[d].x, Alo[d].y, Alo[d].z, Alo[d].w, Ahi[d] };
                    float v0 = v[0], v1 = v[1], v2 = v[2], v3 = v[3], v4 = v[4];
                    float nv[5];
                    unsigned word = 0;
#pragma unroll
                    for (int j = 0; j < 5; j++) {
                        float x0 = v0 + T[j];
                        float x1 = v1 + T[5 + j];
                        float x2 = v2 + T[10 + j];
                        float x3 = v3 + T[15 + j];
                        float x4 = v4 + T[20 + j];
                        float m = fmaxf(fmaxf(fmaxf(x0, x1), fmaxf(x2, x3)), x4);
                        int idx = x0 >= m ? 0 : x1 >= m ? 1 : x2 >= m ? 2 : x3 >= m ? 3 : 4;
                        nv[j] = m + em[j];
                        word |= (unsigned)idx << (3 * j);
                    }
#pragma unroll
                    for (int j = 0; j < 5; j++) v[j] = nv[j];
                    g_bp[(t - 1) * B_ + b] = word;
                }
            }
#pragma unroll
            for (int d = 0; d < 4; d++) { Alo[d] = Blo[d]; Ahi[d] = Bhi[d]; }
        }

        // final argmax (first-index semantics)
        float f0 = v[0] + en[0], f1 = v[1] + en[1], f2 = v[2] + en[2],
              f3 = v[3] + en[3], f4 = v[4] + en[4];
        float m = fmaxf(fmaxf(fmaxf(f0, f1), fmaxf(f2, f3)), f4);
        int last = f0 >= m ? 0 : f1 >= m ? 1 : f2 >= m ? 2 : f3 >= m ? 3 : 4;

        if (path_off >= 0) {
            out[path_off + b * S_ + (S_ - 1)] = (float)last;
            int tag = last;
#pragma unroll 1
            for (int kb = S_ - 2; kb >= 0; kb -= 8) {
                unsigned w[8];
#pragma unroll
                for (int d = 0; d < 8; d++) {
                    int k = kb - d;
                    if (k >= 0) w[d] = g_bp[k * B_ + b];
                }
#pragma unroll
                for (int d = 0; d < 8; d++) {
                    int k = kb - d;
                    if (k >= 0) {
                        tag = (int)((w[d] >> (tag * 3)) & 7u);
                        out[path_off + b * S_ + k] = (float)tag;
                    }
                }
            }
        }
    }
}

// ---------------------------------------------------------------------------
extern "C" void kernel_launch(void* const* d_in, const int* in_sizes, int n_in,
                              void* d_out, int out_size) {
    const float* feats   = (const float*)d_in[0];
    const int*   labels  = (const int*)d_in[1];
    // d_in[2] = mask (all true for this problem; unused)
    const float* W       = (const float*)d_in[3];
    const float* bias    = (const float*)d_in[4];
    const float* start_t = (const float*)d_in[5];
    const float* end_t   = (const float*)d_in[6];
    const float* trans   = (const float*)d_in[7];
    const float* weights = (const float*)d_in[8];
    float* out = (float*)d_out;

    int loss_off = 0, path_off = -1;
    if (out_size >= 1 + B_ * S_)      { loss_off = 0;  path_off = 1; }
    else if (out_size == B_ * S_)     { loss_off = -1; path_off = 0; }

    k_emit<<<1024, 256>>>(feats, W, bias);
    k_crf<<<2, 64>>>(labels, start_t, end_t, trans, weights, out, loss_off, path_off);
}

// round 6
// speedup vs baseline: 1.7562x; 1.7562x over previous
#include <cuda_runtime.h>

#define B_ 64
#define S_ 512
#define H_ 1024
#define L_ 5
#define CH_ 32
#define CL_ 16

// ---- static device scratch (no allocation) ----
__device__ float4   g_em4[S_ * B_];        // emissions states 0-3, [t][b]
__device__ float    g_em1[S_ * B_];        // emission state 4,    [t][b]
__device__ float    g_Pf[CH_ * 25 * B_];   // fwd chunk matrices, exp(G - g0_row), [k][i*5+j][b]
__device__ float    g_g0[CH_ * 5 * B_];    // fwd row offsets G[i][0], [k][i][b]
__device__ float    g_Gv[CH_ * 25 * B_];   // viterbi chunk matrices (max-plus), [k][i*5+j][b]
__device__ float    g_vb[CH_ * 5 * B_];    // viterbi vector at chunk entry, [k][i][b]
__device__ float    g_np[CH_ * B_];        // numerator partial sums, [k][b]
__device__ unsigned g_bp[(S_ - 1) * B_];   // packed backpointers (3 bits x 5 states)
__device__ int      g_last[B_];            // final viterbi tag

#define SEL5(a0, a1, a2, a3, a4, i) \
    ((i) == 0 ? (a0) : (i) == 1 ? (a1) : (i) == 2 ? (a2) : (i) == 3 ? (a3) : (a4))

// ---------------------------------------------------------------------------
// K1: emissions = relu(feats @ W + b), dense layout g_em4/g_em1 [t][b]
// One warp = 4 rows, W transposed in shared, feats double-buffered for MLP.
// ---------------------------------------------------------------------------
__global__ __launch_bounds__(256) void k_emit(const float* __restrict__ feats,
                                              const float* __restrict__ W,
                                              const float* __restrict__ bias) {
    __shared__ float sw[L_ * H_];   // sw[l*H + h] = W[h*L + l]
    int tid = threadIdx.x;
    for (int i = tid; i < L_ * H_; i += 256) {
        int h = i / L_, l = i % L_;
        sw[l * H_ + h] = W[i];
    }
    __syncthreads();

    int warp = tid >> 5, lane = tid & 31;
    int r0 = (blockIdx.x * 8 + warp) * 4;

    float acc[4][5];
#pragma unroll
    for (int r = 0; r < 4; r++)
#pragma unroll
        for (int l = 0; l < 5; l++) acc[r][l] = 0.f;

    float4 xc[4];
#pragma unroll
    for (int r = 0; r < 4; r++)
        xc[r] = *reinterpret_cast<const float4*>(feats + (size_t)(r0 + r) * H_ + lane * 4);

#pragma unroll 1
    for (int k = 0; k < 8; k++) {
        float4 xn[4];
#pragma unroll
        for (int r = 0; r < 4; r++) xn[r] = make_float4(0.f, 0.f, 0.f, 0.f);
        if (k < 7) {
            int col = (k + 1) * 128 + lane * 4;
#pragma unroll
            for (int r = 0; r < 4; r++)
                xn[r] = *reinterpret_cast<const float4*>(feats + (size_t)(r0 + r) * H_ + col);
        }
        int col = k * 128 + lane * 4;
#pragma unroll
        for (int l = 0; l < 5; l++) {
            float4 w = *reinterpret_cast<const float4*>(sw + l * H_ + col);
#pragma unroll
            for (int r = 0; r < 4; r++)
                acc[r][l] = fmaf(xc[r].w, w.w,
                            fmaf(xc[r].z, w.z,
                            fmaf(xc[r].y, w.y,
                            fmaf(xc[r].x, w.x, acc[r][l]))));
        }
#pragma unroll
        for (int r = 0; r < 4; r++) xc[r] = xn[r];
    }

#pragma unroll
    for (int r = 0; r < 4; r++)
#pragma unroll
        for (int l = 0; l < 5; l++) {
#pragma unroll
            for (int off = 16; off > 0; off >>= 1)
                acc[r][l] += __shfl_xor_sync(0xffffffffu, acc[r][l], off);
        }

    if (lane == 0) {
        float bb[5];
#pragma unroll
        for (int l = 0; l < 5; l++) bb[l] = __ldg(bias + l);
#pragma unroll
        for (int r = 0; r < 4; r++) {
            int row = r0 + r;
            int b = row >> 9;
            int s = row & 511;
            float v0 = fmaxf(acc[r][0] + bb[0], 0.f);
            float v1 = fmaxf(acc[r][1] + bb[1], 0.f);
            float v2 = fmaxf(acc[r][2] + bb[2], 0.f);
            float v3 = fmaxf(acc[r][3] + bb[3], 0.f);
            float v4 = fmaxf(acc[r][4] + bb[4], 0.f);
            g_em4[s * B_ + b] = make_float4(v0, v1, v2, v3);
            g_em1[s * B_ + b] = v4;
        }
    }
}

// ---------------------------------------------------------------------------
// K2: phase A — per-(batch, chunk) transfer matrices, fully parallel.
//   blocks 0..31  : forward (log-sum-exp) matrices + numerator partials
//   blocks 32..63 : viterbi (max-plus) matrices
// block = chunk, thread = batch (coalesced [.][b] accesses).
// ---------------------------------------------------------------------------
__global__ __launch_bounds__(64) void k_phaseA(const int* __restrict__ labels,
                                               const float* __restrict__ trans,
                                               const float* __restrict__ weights) {
    __shared__ float s_trans[25];
    int b = threadIdx.x;
    if (b < 25) s_trans[b] = __ldg(trans + b);
    __syncthreads();

    if (blockIdx.x < CH_) {
        // ----- forward chunk -----
        int k = blockIdx.x;
        int t0 = 1 + CL_ * k;
        int nsteps = min(CL_, S_ - t0);

        float E[25];
#pragma unroll
        for (int i = 0; i < 25; i++) E[i] = __expf(s_trans[i]);
        float wt[5];
#pragma unroll
        for (int l = 0; l < 5; l++) wt[l] = __ldg(weights + l);

        // first step (t0): G = trans + em
        float4 c4 = g_em4[t0 * B_ + b];
        float  c1 = g_em1[t0 * B_ + b];
        float em0 = c4.x, em1v = c4.y, em2 = c4.z, em3 = c4.w, em4v = c1;
        float G[25];
#pragma unroll
        for (int i = 0; i < 5; i++) {
            G[i * 5 + 0] = s_trans[i * 5 + 0] + em0;
            G[i * 5 + 1] = s_trans[i * 5 + 1] + em1v;
            G[i * 5 + 2] = s_trans[i * 5 + 2] + em2;
            G[i * 5 + 3] = s_trans[i * 5 + 3] + em3;
            G[i * 5 + 4] = s_trans[i * 5 + 4] + em4v;
        }
        int lp = __ldg(labels + b * S_ + t0 - 1);
        int lc = __ldg(labels + b * S_ + t0);
        float emv = SEL5(em0, em1v, em2, em3, em4v, lc);
        float np = SEL5(wt[0], wt[1], wt[2], wt[3], wt[4], lc) * emv + s_trans[lp * 5 + lc];
        lp = lc;

        float4 n4 = make_float4(0.f, 0.f, 0.f, 0.f);
        float n1 = 0.f; int nl = 0;
        if (nsteps > 1) {
            n4 = g_em4[(t0 + 1) * B_ + b];
            n1 = g_em1[(t0 + 1) * B_ + b];
            nl = __ldg(labels + b * S_ + t0 + 1);
        }

#pragma unroll 1
        for (int d = 1; d < nsteps; d++) {
            float4 u4 = n4; float u1 = n1; int ul = nl;
            if (d + 1 < nsteps) {
                n4 = g_em4[(t0 + d + 1) * B_ + b];
                n1 = g_em1[(t0 + d + 1) * B_ + b];
                nl = __ldg(labels + b * S_ + t0 + d + 1);
            }
            float e0 = u4.x, e1 = u4.y, e2 = u4.z, e3 = u4.w, e4 = u1;
            float nG[25];
#pragma unroll
            for (int i = 0; i < 5; i++) {
                float g0 = G[i * 5 + 0];
                float x1 = __expf(G[i * 5 + 1] - g0);
                float x2 = __expf(G[i * 5 + 2] - g0);
                float x3 = __expf(G[i * 5 + 3] - g0);
                float x4 = __expf(G[i * 5 + 4] - g0);
#pragma unroll
                for (int j = 0; j < 5; j++) {
                    float s = fmaf(x4, E[20 + j],
                              fmaf(x3, E[15 + j],
                              fmaf(x2, E[10 + j],
                              fmaf(x1, E[5 + j], E[j]))));
                    nG[i * 5 + j] = g0 + __logf(s);
                }
            }
#pragma unroll
            for (int i = 0; i < 5; i++) {
                G[i * 5 + 0] = nG[i * 5 + 0] + e0;
                G[i * 5 + 1] = nG[i * 5 + 1] + e1;
                G[i * 5 + 2] = nG[i * 5 + 2] + e2;
                G[i * 5 + 3] = nG[i * 5 + 3] + e3;
                G[i * 5 + 4] = nG[i * 5 + 4] + e4;
            }
            float ev = SEL5(e0, e1, e2, e3, e4, ul);
            float wv = SEL5(wt[0], wt[1], wt[2], wt[3], wt[4], ul);
            np = fmaf(wv, ev, np) + s_trans[lp * 5 + ul];
            lp = ul;
        }

        g_np[k * B_ + b] = np;
#pragma unroll
        for (int i = 0; i < 5; i++) {
            float g0 = G[i * 5 + 0];
            g_g0[(k * 5 + i) * B_ + b] = g0;
#pragma unroll
            for (int j = 0; j < 5; j++)
                g_Pf[(k * 25 + i * 5 + j) * B_ + b] = __expf(G[i * 5 + j] - g0);
        }
    } else {
        // ----- viterbi chunk (max-plus matrix) -----
        int k = blockIdx.x - CH_;
        int t0 = 1 + CL_ * k;
        int nsteps = min(CL_, S_ - t0);

        float T[25];
#pragma unroll
        for (int i = 0; i < 25; i++) T[i] = s_trans[i];

        float4 c4 = g_em4[t0 * B_ + b];
        float  c1 = g_em1[t0 * B_ + b];
        float G[25];
#pragma unroll
        for (int i = 0; i < 5; i++) {
            G[i * 5 + 0] = T[i * 5 + 0] + c4.x;
            G[i * 5 + 1] = T[i * 5 + 1] + c4.y;
            G[i * 5 + 2] = T[i * 5 + 2] + c4.z;
            G[i * 5 + 3] = T[i * 5 + 3] + c4.w;
            G[i * 5 + 4] = T[i * 5 + 4] + c1;
        }

        float4 n4 = make_float4(0.f, 0.f, 0.f, 0.f);
        float n1 = 0.f;
        if (nsteps > 1) {
            n4 = g_em4[(t0 + 1) * B_ + b];
            n1 = g_em1[(t0 + 1) * B_ + b];
        }

#pragma unroll 1
        for (int d = 1; d < nsteps; d++) {
            float4 u4 = n4; float u1 = n1;
            if (d + 1 < nsteps) {
                n4 = g_em4[(t0 + d + 1) * B_ + b];
                n1 = g_em1[(t0 + d + 1) * B_ + b];
            }
            float em[5] = { u4.x, u4.y, u4.z, u4.w, u1 };
            float nG[25];
#pragma unroll
            for (int i = 0; i < 5; i++) {
#pragma unroll
                for (int j = 0; j < 5; j++) {
                    float m = fmaxf(fmaxf(fmaxf(G[i * 5 + 0] + T[j],
                                                G[i * 5 + 1] + T[5 + j]),
                                          fmaxf(G[i * 5 + 2] + T[10 + j],
                                                G[i * 5 + 3] + T[15 + j])),
                                    G[i * 5 + 4] + T[20 + j]);
                    nG[i * 5 + j] = m + em[j];
                }
            }
#pragma unroll
            for (int e = 0; e < 25; e++) G[e] = nG[e];
        }
#pragma unroll
        for (int e = 0; e < 25; e++) g_Gv[(k * 25 + e) * B_ + b] = G[e];
    }
}

// ---------------------------------------------------------------------------
// K3: phase B — sequential composition across 32 chunks (cheap).
//   threads 0..63  : forward alpha composition + numerator + loss
//   threads 64..127: viterbi vector composition + boundary storage + last tag
// ---------------------------------------------------------------------------
__global__ __launch_bounds__(128) void k_phaseB(const int* __restrict__ labels,
                                                const float* __restrict__ start_t,
                                                const float* __restrict__ end_t,
                                                const float* __restrict__ weights,
                                                float* __restrict__ out,
                                                int loss_off) {
    __shared__ float s_red[2];
    int tid = threadIdx.x;

    if (tid < 64) {
        int b = tid;
        float st[5], en[5], wt[5];
#pragma unroll
        for (int l = 0; l < 5; l++) {
            st[l] = __ldg(start_t + l);
            en[l] = __ldg(end_t + l);
            wt[l] = __ldg(weights + l);
        }
        float4 e4 = g_em4[b];
        float  e1 = g_em1[b];
        float em0[5] = { e4.x, e4.y, e4.z, e4.w, e1 };
        float a[5];
#pragma unroll
        for (int j = 0; j < 5; j++) a[j] = st[j] + em0[j];

        int l0 = __ldg(labels + b * S_);
        float num = SEL5(st[0], st[1], st[2], st[3], st[4], l0)
                  + SEL5(wt[0], wt[1], wt[2], wt[3], wt[4], l0)
                  * SEL5(em0[0], em0[1], em0[2], em0[3], em0[4], l0);

        float Pc[25], g0c[5], npc;
#pragma unroll
        for (int e = 0; e < 25; e++) Pc[e] = g_Pf[e * B_ + b];
#pragma unroll
        for (int i = 0; i < 5; i++) g0c[i] = g_g0[i * B_ + b];
        npc = g_np[b];

#pragma unroll 1
        for (int k = 0; k < CH_; k++) {
            float Pn[25], g0n[5], npn = 0.f;
#pragma unroll
            for (int e = 0; e < 25; e++) Pn[e] = 0.f;
#pragma unroll
            for (int i = 0; i < 5; i++) g0n[i] = 0.f;
            if (k < CH_ - 1) {
#pragma unroll
                for (int e = 0; e < 25; e++) Pn[e] = g_Pf[((k + 1) * 25 + e) * B_ + b];
#pragma unroll
                for (int i = 0; i < 5; i++) g0n[i] = g_g0[((k + 1) * 5 + i) * B_ + b];
                npn = g_np[(k + 1) * B_ + b];
            }
            float ref = a[0] + g0c[0];
            float d1 = __expf(a[1] + g0c[1] - ref);
            float d2 = __expf(a[2] + g0c[2] - ref);
            float d3 = __expf(a[3] + g0c[3] - ref);
            float d4 = __expf(a[4] + g0c[4] - ref);
#pragma unroll
            for (int j = 0; j < 5; j++) {
                float s = fmaf(d4, Pc[20 + j],
                          fmaf(d3, Pc[15 + j],
                          fmaf(d2, Pc[10 + j],
                          fmaf(d1, Pc[5 + j], Pc[j]))));
                a[j] = ref + __logf(s);
            }
            num += npc;
#pragma unroll
            for (int e = 0; e < 25; e++) Pc[e] = Pn[e];
#pragma unroll
            for (int i = 0; i < 5; i++) g0c[i] = g0n[i];
            npc = npn;
        }

        int llast = __ldg(labels + b * S_ + S_ - 1);
        num += SEL5(en[0], en[1], en[2], en[3], en[4], llast);

        float base = a[0] + en[0];
        float zs = 1.f + __expf(a[1] + en[1] - base) + __expf(a[2] + en[2] - base)
                       + __expf(a[3] + en[3] - base) + __expf(a[4] + en[4] - base);
        float logZ = base + __logf(zs);

        float dlt = num - logZ;
#pragma unroll
        for (int off = 16; off > 0; off >>= 1)
            dlt += __shfl_xor_sync(0xffffffffu, dlt, off);
        if ((tid & 31) == 0) s_red[tid >> 5] = dlt;
    } else {
        int b = tid - 64;
        float en[5], st[5];
#pragma unroll
        for (int l = 0; l < 5; l++) { en[l] = __ldg(end_t + l); st[l] = __ldg(start_t + l); }
        float4 e4 = g_em4[b];
        float  e1 = g_em1[b];
        float v[5] = { st[0] + e4.x, st[1] + e4.y, st[2] + e4.z, st[3] + e4.w, st[4] + e1 };

        float Gc[25];
#pragma unroll
        for (int e = 0; e < 25; e++) Gc[e] = g_Gv[e * B_ + b];

#pragma unroll 1
        for (int k = 0; k < CH_; k++) {
            float Gn[25];
#pragma unroll
            for (int e = 0; e < 25; e++) Gn[e] = 0.f;
            if (k < CH_ - 1) {
#pragma unroll
                for (int e = 0; e < 25; e++) Gn[e] = g_Gv[((k + 1) * 25 + e) * B_ + b];
            }
#pragma unroll
            for (int i = 0; i < 5; i++) g_vb[(k * 5 + i) * B_ + b] = v[i];
            float nv[5];
#pragma unroll
            for (int j = 0; j < 5; j++) {
                nv[j] = fmaxf(fmaxf(fmaxf(v[0] + Gc[j], v[1] + Gc[5 + j]),
                                    fmaxf(v[2] + Gc[10 + j], v[3] + Gc[15 + j])),
                              v[4] + Gc[20 + j]);
            }
#pragma unroll
            for (int j = 0; j < 5; j++) v[j] = nv[j];
#pragma unroll
            for (int e = 0; e < 25; e++) Gc[e] = Gn[e];
        }

        float f0 = v[0] + en[0], f1 = v[1] + en[1], f2 = v[2] + en[2],
              f3 = v[3] + en[3], f4 = v[4] + en[4];
        float m = fmaxf(fmaxf(fmaxf(f0, f1), fmaxf(f2, f3)), f4);
        g_last[b] = f0 >= m ? 0 : f1 >= m ? 1 : f2 >= m ? 2 : f3 >= m ? 3 : 4;
    }
    __syncthreads();
    if (tid == 0 && loss_off >= 0)
        out[loss_off] = -(s_red[0] + s_red[1]) * (1.0f / 32768.0f);
}

// ---------------------------------------------------------------------------
// K4: phase C — regenerate per-step backpointers in parallel (block = chunk).
// ---------------------------------------------------------------------------
__global__ __launch_bounds__(64) void k_bpgen(const float* __restrict__ trans) {
    __shared__ float s_trans[25];
    int b = threadIdx.x;
    if (b < 25) s_trans[b] = __ldg(trans + b);
    __syncthreads();

    int k = blockIdx.x;
    int t0 = 1 + CL_ * k;
    int nsteps = min(CL_, S_ - t0);

    float T[25];
#pragma unroll
    for (int i = 0; i < 25; i++) T[i] = s_trans[i];

    float v[5];
#pragma unroll
    for (int i = 0; i < 5; i++) v[i] = g_vb[(k * 5 + i) * B_ + b];

    float4 n4 = g_em4[t0 * B_ + b];
    float  n1 = g_em1[t0 * B_ + b];

#pragma unroll 1
    for (int d = 0; d < nsteps; d++) {
        float4 u4 = n4; float u1 = n1;
        if (d + 1 < nsteps) {
            n4 = g_em4[(t0 + d + 1) * B_ + b];
            n1 = g_em1[(t0 + d + 1) * B_ + b];
        }
        float em[5] = { u4.x, u4.y, u4.z, u4.w, u1 };
        float nv[5];
        unsigned word = 0;
#pragma unroll
        for (int j = 0; j < 5; j++) {
            float x0 = v[0] + T[j];
            float x1 = v[1] + T[5 + j];
            float x2 = v[2] + T[10 + j];
            float x3 = v[3] + T[15 + j];
            float x4 = v[4] + T[20 + j];
            float m = fmaxf(fmaxf(fmaxf(x0, x1), fmaxf(x2, x3)), x4);
            int idx = x0 >= m ? 0 : x1 >= m ? 1 : x2 >= m ? 2 : x3 >= m ? 3 : 4;
            nv[j] = m + em[j];
            word |= (unsigned)idx << (3 * j);
        }
#pragma unroll
        for (int j = 0; j < 5; j++) v[j] = nv[j];
        g_bp[(t0 + d - 1) * B_ + b] = word;
    }
}

// ---------------------------------------------------------------------------
// K5: phase D — backtrace (cheap sequential shifts, loads batch-prefetched).
// ---------------------------------------------------------------------------
__global__ __launch_bounds__(64) void k_backtrace(float* __restrict__ out, int path_off) {
    int b = threadIdx.x;
    if (path_off < 0) return;
    int tag = g_last[b];
    out[path_off + b * S_ + (S_ - 1)] = (float)tag;
#pragma unroll 1
    for (int kb = S_ - 2; kb >= 0; kb -= 8) {
        unsigned w[8];
#pragma unroll
        for (int d = 0; d < 8; d++) w[d] = 0u;
#pragma unroll
        for (int d = 0; d < 8; d++) {
            int k = kb - d;
            if (k >= 0) w[d] = g_bp[k * B_ + b];
        }
#pragma unroll
        for (int d = 0; d < 8; d++) {
            int k = kb - d;
            if (k >= 0) {
                tag = (int)((w[d] >> (tag * 3)) & 7u);
                out[path_off + b * S_ + k] = (float)tag;
            }
        }
    }
}

// ---------------------------------------------------------------------------
extern "C" void kernel_launch(void* const* d_in, const int* in_sizes, int n_in,
                              void* d_out, int out_size) {
    const float* feats   = (const float*)d_in[0];
    const int*   labels  = (const int*)d_in[1];
    // d_in[2] = mask (all true; unused)
    const float* W       = (const float*)d_in[3];
    const float* bias    = (const float*)d_in[4];
    const float* start_t = (const float*)d_in[5];
    const float* end_t   = (const float*)d_in[6];
    const float* trans   = (const float*)d_in[7];
    const float* weights = (const float*)d_in[8];
    float* out = (float*)d_out;

    int loss_off = 0, path_off = -1;
    if (out_size >= 1 + B_ * S_)      { loss_off = 0;  path_off = 1; }
    else if (out_size == B_ * S_)     { loss_off = -1; path_off = 0; }

    k_emit<<<1024, 256>>>(feats, W, bias);
    k_phaseA<<<2 * CH_, 64>>>(labels, trans, weights);
    k_phaseB<<<1, 128>>>(labels, start_t, end_t, weights, out, loss_off);
    k_bpgen<<<CH_, 64>>>(trans);
    k_backtrace<<<1, 64>>>(out, path_off);
}

// round 7
// speedup vs baseline: 2.5849x; 1.4719x over previous
#include <cuda_runtime.h>

#define B_   64
#define S_   512
#define H_   1024
#define L_   5
#define CH_  32
#define CL_  16
#define NBLK 128
#define NTHR 256

// ---- static device scratch ----
__device__ float4   g_em4[S_ * B_];        // emissions states 0-3, [t][b]
__device__ float    g_em1[S_ * B_];        // emission state 4,    [t][b]
__device__ float    g_Pf[CH_ * 25 * B_];   // fwd chunk matrices exp(G - g0_row)
__device__ float    g_g0[CH_ * 5 * B_];    // fwd row offsets
__device__ float    g_Gv[CH_ * 25 * B_];   // viterbi chunk matrices (max-plus)
__device__ float    g_vb[CH_ * 5 * B_];    // viterbi vector at chunk entry
__device__ float    g_np[CH_ * B_];        // numerator partials
__device__ unsigned g_bp[(S_ - 1) * B_];   // packed backpointers (3b x 5)
__device__ unsigned g_map[CH_ * B_];       // per-chunk tag->tag map (3b x 5)
__device__ int      g_last[B_];            // final viterbi tag
__device__ int          g_cnt;             // grid barrier
__device__ volatile int g_gen;

#define SEL5(a0, a1, a2, a3, a4, i) \
    ((i) == 0 ? (a0) : (i) == 1 ? (a1) : (i) == 2 ? (a2) : (i) == 3 ? (a3) : (a4))

__device__ __forceinline__ void gridbar() {
    __syncthreads();
    __threadfence();
    if (threadIdx.x == 0) {
        int gen = g_gen;
        if (atomicAdd(&g_cnt, 1) == NBLK - 1) {
            g_cnt = 0;
            __threadfence();
            g_gen = gen + 1;
        } else {
            while (g_gen == gen) __nanosleep(64);
        }
    }
    __syncthreads();
}

// ---------------------------------------------------------------------------
// ONE fused kernel: emit -> bar -> phaseA -> bar -> phaseB -> bar -> bpgen+map
// -> bar -> parallel path emit (+ loss write).
// ---------------------------------------------------------------------------
__global__ __launch_bounds__(NTHR, 1) void k_fused(
    const float* __restrict__ feats,
    const int*   __restrict__ labels,
    const float* __restrict__ W,
    const float* __restrict__ bias,
    const float* __restrict__ start_t,
    const float* __restrict__ end_t,
    const float* __restrict__ trans,
    const float* __restrict__ weights,
    float* __restrict__ out,
    int loss_off, int path_off)
{
    __shared__ float sw[L_ * H_];     // W transposed: sw[l*H + h]
    __shared__ float s_trans[25];
    __shared__ float s_red[2];

    int tid = threadIdx.x;
    for (int i = tid; i < L_ * H_; i += NTHR) {
        int h = i / L_, l = i % L_;
        sw[l * H_ + h] = W[i];
    }
    if (tid < 25) s_trans[tid] = __ldg(trans + tid);
    __syncthreads();

    // ================= stage E: emissions GEMM (all blocks) =================
    {
        int warp = tid >> 5, lane = tid & 31;
        int wbase = (blockIdx.x * 8 + warp) * 32;   // 32 rows per warp

#pragma unroll 1
        for (int g = 0; g < 8; g++) {
            int r0 = wbase + g * 4;
            const float* p0 = feats + (size_t)r0 * H_ + lane * 4;

            float4 b0[4], b1[4], b2[4];
#pragma unroll
            for (int r = 0; r < 4; r++) b0[r] = *reinterpret_cast<const float4*>(p0 + (size_t)r * H_);
#pragma unroll
            for (int r = 0; r < 4; r++) b1[r] = *reinterpret_cast<const float4*>(p0 + (size_t)r * H_ + 128);
#pragma unroll
            for (int r = 0; r < 4; r++) b2[r] = *reinterpret_cast<const float4*>(p0 + (size_t)r * H_ + 256);

            float acc[4][5];
#pragma unroll
            for (int r = 0; r < 4; r++)
#pragma unroll
                for (int l = 0; l < 5; l++) acc[r][l] = 0.f;

#pragma unroll
            for (int k = 0; k < 8; k++) {
                float4 x[4];
#pragma unroll
                for (int r = 0; r < 4; r++)
                    x[r] = (k % 3 == 0) ? b0[r] : (k % 3 == 1) ? b1[r] : b2[r];
                if (k + 3 < 8) {
                    int col = (k + 3) * 128;
#pragma unroll
                    for (int r = 0; r < 4; r++) {
                        float4 v = *reinterpret_cast<const float4*>(p0 + (size_t)r * H_ + col);
                        if (k % 3 == 0) b0[r] = v; else if (k % 3 == 1) b1[r] = v; else b2[r] = v;
                    }
                }
                int col = k * 128 + lane * 4;
#pragma unroll
                for (int l = 0; l < 5; l++) {
                    float4 w = *reinterpret_cast<const float4*>(sw + l * H_ + col);
#pragma unroll
                    for (int r = 0; r < 4; r++)
                        acc[r][l] = fmaf(x[r].w, w.w,
                                    fmaf(x[r].z, w.z,
                                    fmaf(x[r].y, w.y,
                                    fmaf(x[r].x, w.x, acc[r][l]))));
                }
            }

#pragma unroll
            for (int r = 0; r < 4; r++)
#pragma unroll
                for (int l = 0; l < 5; l++) {
#pragma unroll
                    for (int off = 16; off > 0; off >>= 1)
                        acc[r][l] += __shfl_xor_sync(0xffffffffu, acc[r][l], off);
                }

            if (lane == 0) {
                float bb[5];
#pragma unroll
                for (int l = 0; l < 5; l++) bb[l] = __ldg(bias + l);
#pragma unroll
                for (int r = 0; r < 4; r++) {
                    int row = r0 + r;
                    int b = row >> 9;
                    int s = row & 511;
                    float v0 = fmaxf(acc[r][0] + bb[0], 0.f);
                    float v1 = fmaxf(acc[r][1] + bb[1], 0.f);
                    float v2 = fmaxf(acc[r][2] + bb[2], 0.f);
                    float v3 = fmaxf(acc[r][3] + bb[3], 0.f);
                    float v4 = fmaxf(acc[r][4] + bb[4], 0.f);
                    g_em4[s * B_ + b] = make_float4(v0, v1, v2, v3);
                    g_em1[s * B_ + b] = v4;
                }
            }
        }
    }
    gridbar();

    // ================= stage A: chunk transfer matrices =================
    if (blockIdx.x < CH_ && tid < 64) {
        // forward chunk
        int b = tid;
        int k = blockIdx.x;
        int t0 = 1 + CL_ * k;
        int nsteps = min(CL_, S_ - t0);

        float E[25];
#pragma unroll
        for (int i = 0; i < 25; i++) E[i] = __expf(s_trans[i]);
        float wt[5];
#pragma unroll
        for (int l = 0; l < 5; l++) wt[l] = __ldg(weights + l);

        float4 c4 = g_em4[t0 * B_ + b];
        float  c1 = g_em1[t0 * B_ + b];
        float em0 = c4.x, em1v = c4.y, em2 = c4.z, em3 = c4.w, em4v = c1;
        float G[25];
#pragma unroll
        for (int i = 0; i < 5; i++) {
            G[i * 5 + 0] = s_trans[i * 5 + 0] + em0;
            G[i * 5 + 1] = s_trans[i * 5 + 1] + em1v;
            G[i * 5 + 2] = s_trans[i * 5 + 2] + em2;
            G[i * 5 + 3] = s_trans[i * 5 + 3] + em3;
            G[i * 5 + 4] = s_trans[i * 5 + 4] + em4v;
        }
        int lp = __ldg(labels + b * S_ + t0 - 1);
        int lc = __ldg(labels + b * S_ + t0);
        float emv = SEL5(em0, em1v, em2, em3, em4v, lc);
        float np = SEL5(wt[0], wt[1], wt[2], wt[3], wt[4], lc) * emv + s_trans[lp * 5 + lc];
        lp = lc;

        float4 n4 = make_float4(0.f, 0.f, 0.f, 0.f);
        float n1 = 0.f; int nl = 0;
        if (nsteps > 1) {
            n4 = g_em4[(t0 + 1) * B_ + b];
            n1 = g_em1[(t0 + 1) * B_ + b];
            nl = __ldg(labels + b * S_ + t0 + 1);
        }

#pragma unroll 1
        for (int d = 1; d < nsteps; d++) {
            float4 u4 = n4; float u1 = n1; int ul = nl;
            if (d + 1 < nsteps) {
                n4 = g_em4[(t0 + d + 1) * B_ + b];
                n1 = g_em1[(t0 + d + 1) * B_ + b];
                nl = __ldg(labels + b * S_ + t0 + d + 1);
            }
            float e0 = u4.x, e1 = u4.y, e2 = u4.z, e3 = u4.w, e4 = u1;
            float nG[25];
#pragma unroll
            for (int i = 0; i < 5; i++) {
                float g0 = G[i * 5 + 0];
                float x1 = __expf(G[i * 5 + 1] - g0);
                float x2 = __expf(G[i * 5 + 2] - g0);
                float x3 = __expf(G[i * 5 + 3] - g0);
                float x4 = __expf(G[i * 5 + 4] - g0);
#pragma unroll
                for (int j = 0; j < 5; j++) {
                    float s = fmaf(x4, E[20 + j],
                              fmaf(x3, E[15 + j],
                              fmaf(x2, E[10 + j],
                              fmaf(x1, E[5 + j], E[j]))));
                    nG[i * 5 + j] = g0 + __logf(s);
                }
            }
#pragma unroll
            for (int i = 0; i < 5; i++) {
                G[i * 5 + 0] = nG[i * 5 + 0] + e0;
                G[i * 5 + 1] = nG[i * 5 + 1] + e1;
                G[i * 5 + 2] = nG[i * 5 + 2] + e2;
                G[i * 5 + 3] = nG[i * 5 + 3] + e3;
                G[i * 5 + 4] = nG[i * 5 + 4] + e4;
            }
            float ev = SEL5(e0, e1, e2, e3, e4, ul);
            float wv = SEL5(wt[0], wt[1], wt[2], wt[3], wt[4], ul);
            np = fmaf(wv, ev, np) + s_trans[lp * 5 + ul];
            lp = ul;
        }

        g_np[k * B_ + b] = np;
#pragma unroll
        for (int i = 0; i < 5; i++) {
            float g0 = G[i * 5 + 0];
            g_g0[(k * 5 + i) * B_ + b] = g0;
#pragma unroll
            for (int j = 0; j < 5; j++)
                g_Pf[(k * 25 + i * 5 + j) * B_ + b] = __expf(G[i * 5 + j] - g0);
        }
    } else if (blockIdx.x >= CH_ && blockIdx.x < 2 * CH_ && tid < 64) {
        // viterbi chunk (max-plus matrix) — arithmetic identical to R6
        int b = tid;
        int k = blockIdx.x - CH_;
        int t0 = 1 + CL_ * k;
        int nsteps = min(CL_, S_ - t0);

        float T[25];
#pragma unroll
        for (int i = 0; i < 25; i++) T[i] = s_trans[i];

        float4 c4 = g_em4[t0 * B_ + b];
        float  c1 = g_em1[t0 * B_ + b];
        float G[25];
#pragma unroll
        for (int i = 0; i < 5; i++) {
            G[i * 5 + 0] = T[i * 5 + 0] + c4.x;
            G[i * 5 + 1] = T[i * 5 + 1] + c4.y;
            G[i * 5 + 2] = T[i * 5 + 2] + c4.z;
            G[i * 5 + 3] = T[i * 5 + 3] + c4.w;
            G[i * 5 + 4] = T[i * 5 + 4] + c1;
        }

        float4 n4 = make_float4(0.f, 0.f, 0.f, 0.f);
        float n1 = 0.f;
        if (nsteps > 1) {
            n4 = g_em4[(t0 + 1) * B_ + b];
            n1 = g_em1[(t0 + 1) * B_ + b];
        }

#pragma unroll 1
        for (int d = 1; d < nsteps; d++) {
            float4 u4 = n4; float u1 = n1;
            if (d + 1 < nsteps) {
                n4 = g_em4[(t0 + d + 1) * B_ + b];
                n1 = g_em1[(t0 + d + 1) * B_ + b];
            }
            float em[5] = { u4.x, u4.y, u4.z, u4.w, u1 };
            float nG[25];
#pragma unroll
            for (int i = 0; i < 5; i++) {
#pragma unroll
                for (int j = 0; j < 5; j++) {
                    float m = fmaxf(fmaxf(fmaxf(G[i * 5 + 0] + T[j],
                                                G[i * 5 + 1] + T[5 + j]),
                                          fmaxf(G[i * 5 + 2] + T[10 + j],
                                                G[i * 5 + 3] + T[15 + j])),
                                    G[i * 5 + 4] + T[20 + j]);
                    nG[i * 5 + j] = m + em[j];
                }
            }
#pragma unroll
            for (int e = 0; e < 25; e++) G[e] = nG[e];
        }
#pragma unroll
        for (int e = 0; e < 25; e++) g_Gv[(k * 25 + e) * B_ + b] = G[e];
    }
    gridbar();

    // ================= stage B: sequential chunk composition (block 0) ======
    if (blockIdx.x == 0 && tid < 128) {
        if (tid < 64) {
            int b = tid;
            float st[5], en[5], wt[5];
#pragma unroll
            for (int l = 0; l < 5; l++) {
                st[l] = __ldg(start_t + l);
                en[l] = __ldg(end_t + l);
                wt[l] = __ldg(weights + l);
            }
            float4 e4 = g_em4[b];
            float  e1 = g_em1[b];
            float em0[5] = { e4.x, e4.y, e4.z, e4.w, e1 };
            float a[5];
#pragma unroll
            for (int j = 0; j < 5; j++) a[j] = st[j] + em0[j];

            int l0 = __ldg(labels + b * S_);
            float num = SEL5(st[0], st[1], st[2], st[3], st[4], l0)
                      + SEL5(wt[0], wt[1], wt[2], wt[3], wt[4], l0)
                      * SEL5(em0[0], em0[1], em0[2], em0[3], em0[4], l0);

            float Pc[25], g0c[5], npc;
#pragma unroll
            for (int e = 0; e < 25; e++) Pc[e] = g_Pf[e * B_ + b];
#pragma unroll
            for (int i = 0; i < 5; i++) g0c[i] = g_g0[i * B_ + b];
            npc = g_np[b];

#pragma unroll 1
            for (int k = 0; k < CH_; k++) {
                float Pn[25], g0n[5], npn = 0.f;
#pragma unroll
                for (int e = 0; e < 25; e++) Pn[e] = 0.f;
#pragma unroll
                for (int i = 0; i < 5; i++) g0n[i] = 0.f;
                if (k < CH_ - 1) {
#pragma unroll
                    for (int e = 0; e < 25; e++) Pn[e] = g_Pf[((k + 1) * 25 + e) * B_ + b];
#pragma unroll
                    for (int i = 0; i < 5; i++) g0n[i] = g_g0[((k + 1) * 5 + i) * B_ + b];
                    npn = g_np[(k + 1) * B_ + b];
                }
                float ref = a[0] + g0c[0];
                float d1 = __expf(a[1] + g0c[1] - ref);
                float d2 = __expf(a[2] + g0c[2] - ref);
                float d3 = __expf(a[3] + g0c[3] - ref);
                float d4 = __expf(a[4] + g0c[4] - ref);
#pragma unroll
                for (int j = 0; j < 5; j++) {
                    float s = fmaf(d4, Pc[20 + j],
                              fmaf(d3, Pc[15 + j],
                              fmaf(d2, Pc[10 + j],
                              fmaf(d1, Pc[5 + j], Pc[j]))));
                    a[j] = ref + __logf(s);
                }
                num += npc;
#pragma unroll
                for (int e = 0; e < 25; e++) Pc[e] = Pn[e];
#pragma unroll
                for (int i = 0; i < 5; i++) g0c[i] = g0n[i];
                npc = npn;
            }

            int llast = __ldg(labels + b * S_ + S_ - 1);
            num += SEL5(en[0], en[1], en[2], en[3], en[4], llast);

            float base = a[0] + en[0];
            float zs = 1.f + __expf(a[1] + en[1] - base) + __expf(a[2] + en[2] - base)
                           + __expf(a[3] + en[3] - base) + __expf(a[4] + en[4] - base);
            float logZ = base + __logf(zs);

            float dlt = num - logZ;
#pragma unroll
            for (int off = 16; off > 0; off >>= 1)
                dlt += __shfl_xor_sync(0xffffffffu, dlt, off);
            if ((tid & 31) == 0) s_red[tid >> 5] = dlt;
        } else {
            int b = tid - 64;
            float en[5], st[5];
#pragma unroll
            for (int l = 0; l < 5; l++) { en[l] = __ldg(end_t + l); st[l] = __ldg(start_t + l); }
            float4 e4 = g_em4[b];
            float  e1 = g_em1[b];
            float v[5] = { st[0] + e4.x, st[1] + e4.y, st[2] + e4.z, st[3] + e4.w, st[4] + e1 };

            float Gc[25];
#pragma unroll
            for (int e = 0; e < 25; e++) Gc[e] = g_Gv[e * B_ + b];

#pragma unroll 1
            for (int k = 0; k < CH_; k++) {
                float Gn[25];
#pragma unroll
                for (int e = 0; e < 25; e++) Gn[e] = 0.f;
                if (k < CH_ - 1) {
#pragma unroll
                    for (int e = 0; e < 25; e++) Gn[e] = g_Gv[((k + 1) * 25 + e) * B_ + b];
                }
#pragma unroll
                for (int i = 0; i < 5; i++) g_vb[(k * 5 + i) * B_ + b] = v[i];
                float nv[5];
#pragma unroll
                for (int j = 0; j < 5; j++) {
                    nv[j] = fmaxf(fmaxf(fmaxf(v[0] + Gc[j], v[1] + Gc[5 + j]),
                                        fmaxf(v[2] + Gc[10 + j], v[3] + Gc[15 + j])),
                                  v[4] + Gc[20 + j]);
                }
#pragma unroll
                for (int j = 0; j < 5; j++) v[j] = nv[j];
#pragma unroll
                for (int e = 0; e < 25; e++) Gc[e] = Gn[e];
            }

            float f0 = v[0] + en[0], f1 = v[1] + en[1], f2 = v[2] + en[2],
                  f3 = v[3] + en[3], f4 = v[4] + en[4];
            float m = fmaxf(fmaxf(fmaxf(f0, f1), fmaxf(f2, f3)), f4);
            g_last[b] = f0 >= m ? 0 : f1 >= m ? 1 : f2 >= m ? 2 : f3 >= m ? 3 : 4;
        }
    }
    gridbar();

    // loss write (s_red now visible to whole block 0)
    if (blockIdx.x == 0 && tid == 0 && loss_off >= 0)
        out[loss_off] = -(s_red[0] + s_red[1]) * (1.0f / 32768.0f);

    // ================= stage C: backpointers + per-chunk tag map ============
    if (blockIdx.x < CH_ && tid < 64) {
        int b = tid;
        int k = blockIdx.x;
        int t0 = 1 + CL_ * k;
        int nsteps = min(CL_, S_ - t0);

        float T[25];
#pragma unroll
        for (int i = 0; i < 25; i++) T[i] = s_trans[i];

        float v[5];
#pragma unroll
        for (int i = 0; i < 5; i++) v[i] = g_vb[(k * 5 + i) * B_ + b];

        // preload ALL chunk emissions (independent loads, issued together)
        float4 E4[CL_]; float E1[CL_];
#pragma unroll
        for (int d = 0; d < CL_; d++) {
            E4[d] = make_float4(0.f, 0.f, 0.f, 0.f); E1[d] = 0.f;
            if (d < nsteps) {
                E4[d] = g_em4[(t0 + d) * B_ + b];
                E1[d] = g_em1[(t0 + d) * B_ + b];
            }
        }

        unsigned Wd[CL_];
#pragma unroll
        for (int d = 0; d < CL_; d++) {
            Wd[d] = 0u;
            if (d < nsteps) {
                float em[5] = { E4[d].x, E4[d].y, E4[d].z, E4[d].w, E1[d] };
                float nv[5];
                unsigned word = 0;
#pragma unroll
                for (int j = 0; j < 5; j++) {
                    float x0 = v[0] + T[j];
                    float x1 = v[1] + T[5 + j];
                    float x2 = v[2] + T[10 + j];
                    float x3 = v[3] + T[15 + j];
                    float x4 = v[4] + T[20 + j];
                    float m = fmaxf(fmaxf(fmaxf(x0, x1), fmaxf(x2, x3)), x4);
                    int idx = x0 >= m ? 0 : x1 >= m ? 1 : x2 >= m ? 2 : x3 >= m ? 3 : 4;
                    nv[j] = m + em[j];
                    word |= (unsigned)idx << (3 * j);
                }
#pragma unroll
                for (int j = 0; j < 5; j++) v[j] = nv[j];
                Wd[d] = word;
                g_bp[(t0 + d - 1) * B_ + b] = word;
            }
        }

        // per-chunk map: tag@chunk_end -> tag@chunk_start (pure integer)
        unsigned mp = 0;
#pragma unroll
        for (int e = 0; e < 5; e++) {
            int tg = e;
#pragma unroll
            for (int d = CL_ - 1; d >= 0; d--)
                if (d < nsteps) tg = (int)((Wd[d] >> (3 * tg)) & 7u);
            mp |= (unsigned)tg << (3 * e);
        }
        g_map[k * B_ + b] = mp;
    }
    gridbar();

    // ================= stage D: parallel path emission ======================
    if (blockIdx.x < CH_ && tid < 64 && path_off >= 0) {
        int b = tid;
        int k = blockIdx.x;
        int t0 = 1 + CL_ * k;
        int nsteps = min(CL_, S_ - t0);
        int t_end = t0 + nsteps;   // 16(k+1) for k<31, 511 for k=31

        // redundantly chain maps 31..k+1 to get this chunk's end tag
        unsigned mp[CH_];
#pragma unroll
        for (int q = 0; q < CH_; q++) {
            mp[q] = 0u;
            if (q > k) mp[q] = g_map[q * B_ + b];
        }
        int c = g_last[b];
#pragma unroll
        for (int q = CH_ - 1; q >= 1; q--)
            if (q > k) c = (int)((mp[q] >> (3 * c)) & 7u);

        if (k == CH_ - 1)
            out[path_off + b * S_ + (S_ - 1)] = (float)g_last[b];

        // preload own bp words, walk backward, emit
        unsigned Wd[CL_];
#pragma unroll
        for (int d = 0; d < CL_; d++) {
            Wd[d] = 0u;
            int t = 16 * k + d;                 // word index range for this chunk
            if (d < nsteps && t < S_ - 1) Wd[d] = g_bp[t * B_ + b];
        }
        int tag = c;                            // tag at t_end
#pragma unroll
        for (int d = CL_ - 1; d >= 0; d--) {
            if (d < nsteps) {
                int t = 16 * k + d;             // emits times t_end-1 .. 16k
                tag = (int)((Wd[d] >> (3 * tag)) & 7u);
                out[path_off + b * S_ + t] = (float)tag;
            }
        }
    }
}

// ---------------------------------------------------------------------------
extern "C" void kernel_launch(void* const* d_in, const int* in_sizes, int n_in,
                              void* d_out, int out_size) {
    const float* feats   = (const float*)d_in[0];
    const int*   labels  = (const int*)d_in[1];
    // d_in[2] = mask (all true; unused)
    const float* W       = (const float*)d_in[3];
    const float* bias    = (const float*)d_in[4];
    const float* start_t = (const float*)d_in[5];
    const float* end_t   = (const float*)d_in[6];
    const float* trans   = (const float*)d_in[7];
    const float* weights = (const float*)d_in[8];
    float* out = (float*)d_out;

    int loss_off = 0, path_off = -1;
    if (out_size >= 1 + B_ * S_)      { loss_off = 0;  path_off = 1; }
    else if (out_size == B_ * S_)     { loss_off = -1; path_off = 0; }

    k_fused<<<NBLK, NTHR>>>(feats, labels, W, bias, start_t, end_t, trans,
                            weights, out, loss_off, path_off);
}